// round 1
// baseline (speedup 1.0000x reference)
#include <cuda_runtime.h>
#include <math.h>

#define DT 1e-3f
#define HGRID 10.0f
#define TS 32

__device__ __forceinline__ int wrapi(int i, int n) {
    if (i < 0) i += n;
    else if (i >= n) i -= n;
    return i;
}

__global__ __launch_bounds__(256)
void wave_step_kernel(const float* __restrict__ vp,  const float* __restrict__ vs,
                      const float* __restrict__ rho,
                      const float* __restrict__ vx,  const float* __restrict__ vz,
                      const float* __restrict__ txx, const float* __restrict__ tzz,
                      const float* __restrict__ txz, const float* __restrict__ dmp,
                      float* __restrict__ out, int B, int NZ, int NX)
{
    // stress fields on rel [-1..32]^2, stored at index rel+1  -> [34][36]
    __shared__ float s_txx[34][36];
    __shared__ float s_tzz[34][36];
    __shared__ float s_txz[34][36];
    // vx_new on rel [0..32]^2 stored at rel            -> [33][36]
    // vz_new on rel [-1..31]^2 stored at rel+1         -> [33][36]
    __shared__ float s_vx[33][36];
    __shared__ float s_vz[33][36];

    const int bb = blockIdx.z;
    const int z0 = blockIdx.y * TS;
    const int x0 = blockIdx.x * TS;
    const int tid = threadIdx.x;
    const size_t plane = (size_t)NZ * NX;

    const float* __restrict__ bvx  = vx  + (size_t)bb * plane;
    const float* __restrict__ bvz  = vz  + (size_t)bb * plane;
    const float* __restrict__ btxx = txx + (size_t)bb * plane;
    const float* __restrict__ btzz = tzz + (size_t)bb * plane;
    const float* __restrict__ btxz = txz + (size_t)bb * plane;

    const float invH = 1.0f / HGRID;

    // ---- Phase 0: load stress halo [-1..32]^2 into shared ----
    #pragma unroll 1
    for (int i = tid; i < 34 * 34; i += 256) {
        int lz = i / 34, lx = i - lz * 34;
        int gz = wrapi(z0 - 1 + lz, NZ);
        int gx = wrapi(x0 - 1 + lx, NX);
        size_t g = (size_t)gz * NX + gx;
        s_txx[lz][lx] = btxx[g];
        s_tzz[lz][lx] = btzz[g];
        s_txz[lz][lx] = btxz[g];
    }
    __syncthreads();

    // ---- Phase 1: velocity update on extended regions ----
    // loop coords (rz, rx) in [0..32]^2:
    //   vx_new at rel (rz, rx)         (needed on [0..32]^2 by stress stencil)
    //   vz_new at rel (rz-1, rx-1)     (needed on [-1..31]^2)
    #pragma unroll 1
    for (int i = tid; i < 33 * 33; i += 256) {
        int rz = i / 33, rx = i - rz * 33;

        {   // vx_new at rel (rz, rx)
            int gz = wrapi(z0 + rz, NZ);
            int gx = wrapi(x0 + rx, NX);
            size_t g = (size_t)gz * NX + gx;
            float c   = 0.5f * DT * dmp[g];
            float inv = 1.0f / (1.0f + c);
            float a   = (1.0f - c) * inv;
            float br  = DT * inv * invH / rho[g];
            float v = a * bvx[g] + br * ((s_txx[rz + 1][rx + 1] - s_txx[rz + 1][rx])
                                       + (s_txz[rz + 1][rx + 1] - s_txz[rz][rx + 1]));
            s_vx[rz][rx] = v;
        }
        {   // vz_new at rel (rz-1, rx-1), stored at (rz, rx)
            int gz = wrapi(z0 + rz - 1, NZ);
            int gx = wrapi(x0 + rx - 1, NX);
            size_t g = (size_t)gz * NX + gx;
            float c   = 0.5f * DT * dmp[g];
            float inv = 1.0f / (1.0f + c);
            float a   = (1.0f - c) * inv;
            float br  = DT * inv * invH / rho[g];
            // rel point p = (rz-1, rx-1); stress smem index = rel+1
            // txz(pz, px+1) -> (rz, rx+1); txz(pz,px) -> (rz, rx)
            // tzz(pz+1, px) -> (rz+1, rx); tzz(pz,px) -> (rz, rx)
            float v = a * bvz[g] + br * ((s_txz[rz][rx + 1] - s_txz[rz][rx])
                                       + (s_tzz[rz + 1][rx] - s_tzz[rz][rx]));
            s_vz[rz][rx] = v;
        }
    }
    __syncthreads();

    // ---- Phase 2: stress update + all writes (interior 32x32) ----
    const size_t bplane = (size_t)B * plane;
    #pragma unroll 1
    for (int i = tid; i < TS * TS; i += 256) {
        int z = i >> 5, x = i & 31;
        int gz = z0 + z, gx = x0 + x;
        if (gz >= NZ || gx >= NX) continue;
        size_t g = (size_t)gz * NX + gx;

        float rr  = rho[g];
        float fvs = vs[g];
        float fvp = vp[g];
        float mu  = rr * fvs * fvs;
        float lam = rr * fvp * fvp - 2.0f * mu;
        float lp2m = lam + 2.0f * mu;

        float c   = 0.5f * DT * dmp[g];
        float inv = 1.0f / (1.0f + c);
        float a   = (1.0f - c) * inv;
        float bco = DT * inv;

        float vx_c  = s_vx[z][x];
        float vz_c  = s_vz[z + 1][x + 1];

        float vx_x  = (s_vx[z][x + 1] - vx_c) * invH;          // dplus x of vx_new
        float vx_zp = (s_vx[z + 1][x] - vx_c) * invH;          // dplus z of vx_new
        float vz_z  = (vz_c - s_vz[z][x + 1]) * invH;          // dminus z of vz_new
        float vz_xm = (vz_c - s_vz[z + 1][x]) * invH;          // dminus x of vz_new

        float txxn = a * s_txx[z + 1][x + 1] + bco * (lp2m * vx_x + lam * vz_z);
        float tzzn = a * s_tzz[z + 1][x + 1] + bco * (lp2m * vz_z + lam * vx_x);
        float txzn = a * s_txz[z + 1][x + 1] + bco * (mu * (vx_zp + vz_xm));

        size_t ob = (size_t)bb * plane + g;
        out[0 * bplane + ob] = vx_c;
        out[1 * bplane + ob] = vz_c;
        out[2 * bplane + ob] = txxn;
        out[3 * bplane + ob] = tzzn;
        out[4 * bplane + ob] = txzn;
    }
}

extern "C" void kernel_launch(void* const* d_in, const int* in_sizes, int n_in,
                              void* d_out, int out_size) {
    const float* vp  = (const float*)d_in[0];
    const float* vs  = (const float*)d_in[1];
    const float* rho = (const float*)d_in[2];
    const float* vx  = (const float*)d_in[3];
    const float* vz  = (const float*)d_in[4];
    const float* txx = (const float*)d_in[5];
    const float* tzz = (const float*)d_in[6];
    const float* txz = (const float*)d_in[7];
    const float* dmp = (const float*)d_in[8];
    float* out = (float*)d_out;

    int plane = in_sizes[0];             // NZ * NX
    int B = in_sizes[3] / plane;         // batch from vx size
    int NX = 1;
    while (NX * NX < plane) NX <<= 1;    // square power-of-two grid (2048)
    int NZ = plane / NX;

    dim3 grid((NX + TS - 1) / TS, (NZ + TS - 1) / TS, B);
    wave_step_kernel<<<grid, 256>>>(vp, vs, rho, vx, vz, txx, tzz, txz, dmp,
                                    out, B, NZ, NX);
}

// round 2
// speedup vs baseline: 1.4691x; 1.4691x over previous
#include <cuda_runtime.h>
#include <math.h>

#define DT 1e-3f
#define HGRID 10.0f
#define TS 32

__device__ __forceinline__ int wrapi(int i, int n) {
    if (i < 0) i += n;
    else if (i >= n) i -= n;
    return i;
}

__global__ __launch_bounds__(256)
void wave_step_kernel(const float* __restrict__ vp,  const float* __restrict__ vs,
                      const float* __restrict__ rho,
                      const float* __restrict__ vx,  const float* __restrict__ vz,
                      const float* __restrict__ txx, const float* __restrict__ tzz,
                      const float* __restrict__ txz, const float* __restrict__ dmp,
                      float* __restrict__ out, int B, int NZ, int NX)
{
    // stress fields on rel [-1..32]^2, stored at [rel+1]  -> [34][36]
    __shared__ float s_txx[34][36];
    __shared__ float s_tzz[34][36];
    __shared__ float s_txz[34][36];
    // vx_new on rel [0..32]^2 stored at [rel]             -> [33][36]
    // vz_new on rel [-1..31]^2 stored at [rel+1]          -> [33][36]
    __shared__ float s_vx[33][36];
    __shared__ float s_vz[33][36];

    const int bb = blockIdx.z;
    const int z0 = blockIdx.y * TS;
    const int x0 = blockIdx.x * TS;
    const int tx = threadIdx.x;          // 0..31
    const int tz = threadIdx.y;          // 0..7
    const size_t plane = (size_t)NZ * NX;

    const float* __restrict__ bvx  = vx  + (size_t)bb * plane;
    const float* __restrict__ bvz  = vz  + (size_t)bb * plane;
    const float* __restrict__ btxx = txx + (size_t)bb * plane;
    const float* __restrict__ btzz = tzz + (size_t)bb * plane;
    const float* __restrict__ btxz = txz + (size_t)bb * plane;

    const float invH = 1.0f / HGRID;

    // ---- Phase 0: load stress halo rel [-1..32]^2 into shared ----
    #pragma unroll
    for (int lz = tz; lz < 34; lz += 8) {
        const int gz = wrapi(z0 - 1 + lz, NZ);
        const float* __restrict__ rTxx = btxx + (size_t)gz * NX;
        const float* __restrict__ rTzz = btzz + (size_t)gz * NX;
        const float* __restrict__ rTxz = btxz + (size_t)gz * NX;
        #pragma unroll
        for (int lx = tx; lx < 34; lx += 32) {
            const int gx = wrapi(x0 - 1 + lx, NX);
            s_txx[lz][lx] = rTxx[gx];
            s_tzz[lz][lx] = rTzz[gx];
            s_txz[lz][lx] = rTxz[gx];
        }
    }
    __syncthreads();

    // ---- Phase 1a: vx_new on rel [0..32]^2 ----
    #pragma unroll
    for (int rz = tz; rz < 33; rz += 8) {
        const int gz = wrapi(z0 + rz, NZ);
        const float* __restrict__ rD = dmp + (size_t)gz * NX;
        const float* __restrict__ rR = rho + (size_t)gz * NX;
        const float* __restrict__ rV = bvx + (size_t)gz * NX;
        #pragma unroll
        for (int rx = tx; rx < 33; rx += 32) {
            const int gx = wrapi(x0 + rx, NX);
            const float c   = 0.5f * DT * rD[gx];
            const float inv = __fdividef(1.0f, 1.0f + c);
            const float a   = (1.0f - c) * inv;
            const float br  = __fdividef(DT * inv * invH, rR[gx]);
            s_vx[rz][rx] = a * rV[gx]
                + br * ((s_txx[rz + 1][rx + 1] - s_txx[rz + 1][rx])
                      + (s_txz[rz + 1][rx + 1] - s_txz[rz][rx + 1]));
        }
    }

    // ---- Phase 1b: vz_new on rel [-1..31]^2, stored at [rel+1] ----
    #pragma unroll
    for (int lz = tz; lz < 33; lz += 8) {
        const int gz = wrapi(z0 - 1 + lz, NZ);
        const float* __restrict__ rD = dmp + (size_t)gz * NX;
        const float* __restrict__ rR = rho + (size_t)gz * NX;
        const float* __restrict__ rV = bvz + (size_t)gz * NX;
        #pragma unroll
        for (int lx = tx; lx < 33; lx += 32) {
            const int gx = wrapi(x0 - 1 + lx, NX);
            const float c   = 0.5f * DT * rD[gx];
            const float inv = __fdividef(1.0f, 1.0f + c);
            const float a   = (1.0f - c) * inv;
            const float br  = __fdividef(DT * inv * invH, rR[gx]);
            s_vz[lz][lx] = a * rV[gx]
                + br * ((s_txz[lz][lx + 1] - s_txz[lz][lx])
                      + (s_tzz[lz + 1][lx] - s_tzz[lz][lx]));
        }
    }
    __syncthreads();

    // ---- Phase 2: stress update + all writes (interior 32x32) ----
    const size_t bplane = (size_t)B * plane;
    #pragma unroll
    for (int z = tz; z < TS; z += 8) {
        const int gz = z0 + z;
        const int gx = x0 + tx;
        const size_t g = (size_t)gz * NX + gx;
        const int x = tx;

        const float rr  = rho[g];
        const float fvs = vs[g];
        const float fvp = vp[g];
        const float mu  = rr * fvs * fvs;
        const float lam = rr * fvp * fvp - 2.0f * mu;
        const float lp2m = lam + 2.0f * mu;

        const float c   = 0.5f * DT * dmp[g];
        const float inv = __fdividef(1.0f, 1.0f + c);
        const float a   = (1.0f - c) * inv;
        const float bco = DT * inv;

        const float vx_c = s_vx[z][x];
        const float vz_c = s_vz[z + 1][x + 1];

        const float vx_x  = (s_vx[z][x + 1] - vx_c) * invH;
        const float vx_zp = (s_vx[z + 1][x] - vx_c) * invH;
        const float vz_z  = (vz_c - s_vz[z][x + 1]) * invH;
        const float vz_xm = (vz_c - s_vz[z + 1][x]) * invH;

        const float txxn = a * s_txx[z + 1][x + 1] + bco * (lp2m * vx_x + lam * vz_z);
        const float tzzn = a * s_tzz[z + 1][x + 1] + bco * (lp2m * vz_z + lam * vx_x);
        const float txzn = a * s_txz[z + 1][x + 1] + bco * (mu * (vx_zp + vz_xm));

        const size_t ob = (size_t)bb * plane + g;
        __stcs(out + 0 * bplane + ob, vx_c);
        __stcs(out + 1 * bplane + ob, vz_c);
        __stcs(out + 2 * bplane + ob, txxn);
        __stcs(out + 3 * bplane + ob, tzzn);
        __stcs(out + 4 * bplane + ob, txzn);
    }
}

extern "C" void kernel_launch(void* const* d_in, const int* in_sizes, int n_in,
                              void* d_out, int out_size) {
    const float* vp  = (const float*)d_in[0];
    const float* vs  = (const float*)d_in[1];
    const float* rho = (const float*)d_in[2];
    const float* vx  = (const float*)d_in[3];
    const float* vz  = (const float*)d_in[4];
    const float* txx = (const float*)d_in[5];
    const float* tzz = (const float*)d_in[6];
    const float* txz = (const float*)d_in[7];
    const float* dmp = (const float*)d_in[8];
    float* out = (float*)d_out;

    int plane = in_sizes[0];             // NZ * NX
    int B = in_sizes[3] / plane;         // batch from vx size
    int NX = 1;
    while (NX * NX < plane) NX <<= 1;    // square power-of-two grid (2048)
    int NZ = plane / NX;

    dim3 block(32, 8);
    dim3 grid((NX + TS - 1) / TS, (NZ + TS - 1) / TS, B);
    wave_step_kernel<<<grid, block>>>(vp, vs, rho, vx, vz, txx, tzz, txz, dmp,
                                      out, B, NZ, NX);
}

// round 3
// speedup vs baseline: 1.5921x; 1.0838x over previous
#include <cuda_runtime.h>
#include <math.h>

#define DT   1e-3f
#define INVH 0.1f
#define TS   32
#define NB   2   // batches per block

__global__ __launch_bounds__(256)
void wave_step_kernel(const float* __restrict__ vp,  const float* __restrict__ vs,
                      const float* __restrict__ rho,
                      const float* __restrict__ vx,  const float* __restrict__ vz,
                      const float* __restrict__ txx, const float* __restrict__ tzz,
                      const float* __restrict__ txz, const float* __restrict__ dmp,
                      float* __restrict__ out, int B, int NZ, int NX)
{
    // stress on rel [-1..32]^2 at [rel+1] -> [34][36]
    __shared__ float s_txx[NB][34][36];
    __shared__ float s_tzz[NB][34][36];
    __shared__ float s_txz[NB][34][36];
    // vx_new on rel [0..32]^2 at [rel]; vz_new on rel [-1..31]^2 at [rel+1]
    __shared__ float s_vx[NB][33][36];
    __shared__ float s_vz[NB][33][36];

    const int bb0 = blockIdx.z * NB;
    const int z0  = blockIdx.y * TS;
    const int x0  = blockIdx.x * TS;
    const int tx  = threadIdx.x;   // 0..31
    const int tz  = threadIdx.y;   // 0..7
    const int plane = NZ * NX;

    const float* __restrict__ pvx[NB];
    const float* __restrict__ pvz[NB];
    const float* __restrict__ ptxx[NB];
    const float* __restrict__ ptzz[NB];
    const float* __restrict__ ptxz[NB];
    #pragma unroll
    for (int n = 0; n < NB; n++) {
        const int off = (bb0 + n) * plane;
        pvx[n]  = vx  + off;  pvz[n]  = vz  + off;
        ptxx[n] = txx + off;  ptzz[n] = tzz + off;  ptxz[n] = txz + off;
    }

    // ---- Phase 0: stress halo rel [-1..32]^2 ----
    #pragma unroll
    for (int lz = tz; lz < 34; lz += 8) {
        int gz = z0 - 1 + lz;
        if (gz < 0) gz += NZ; else if (gz >= NZ) gz -= NZ;
        const int rowc = gz * NX;
        {   // interior columns lx = tx+1, gx = x0+tx (never wraps)
            const int g = rowc + x0 + tx;
            const int lx = tx + 1;
            #pragma unroll
            for (int n = 0; n < NB; n++) {
                s_txx[n][lz][lx] = ptxx[n][g];
                s_tzz[n][lz][lx] = ptzz[n][g];
                s_txz[n][lz][lx] = ptxz[n][g];
            }
        }
        if (tx < 2) {   // edges: lx=0 (gx=x0-1) and lx=33 (gx=x0+32)
            int gx = (tx == 0) ? (x0 - 1) : (x0 + 32);
            if (gx < 0) gx += NX; else if (gx >= NX) gx -= NX;
            const int lx = (tx == 0) ? 0 : 33;
            const int g = rowc + gx;
            #pragma unroll
            for (int n = 0; n < NB; n++) {
                s_txx[n][lz][lx] = ptxx[n][g];
                s_tzz[n][lz][lx] = ptzz[n][g];
                s_txz[n][lz][lx] = ptxz[n][g];
            }
        }
    }
    __syncthreads();

    // ---- Phase 1a: vx_new on rel [0..32]^2 ----
    #pragma unroll
    for (int rz = tz; rz < 33; rz += 8) {
        int gz = z0 + rz;
        if (gz >= NZ) gz -= NZ;
        const int rowc = gz * NX;
        {   const int rx = tx;
            const int g = rowc + x0 + tx;
            const float c   = 0.5f * DT * dmp[g];
            const float inv = __fdividef(1.0f, 1.0f + c);
            const float a   = (1.0f - c) * inv;
            const float br  = __fdividef(DT * inv * INVH, rho[g]);
            #pragma unroll
            for (int n = 0; n < NB; n++) {
                s_vx[n][rz][rx] = a * pvx[n][g]
                    + br * ((s_txx[n][rz + 1][rx + 1] - s_txx[n][rz + 1][rx])
                          + (s_txz[n][rz + 1][rx + 1] - s_txz[n][rz][rx + 1]));
            }
        }
        if (tx == 0) {   // rx = 32
            int gx = x0 + 32; if (gx >= NX) gx -= NX;
            const int g = rowc + gx;
            const float c   = 0.5f * DT * dmp[g];
            const float inv = __fdividef(1.0f, 1.0f + c);
            const float a   = (1.0f - c) * inv;
            const float br  = __fdividef(DT * inv * INVH, rho[g]);
            #pragma unroll
            for (int n = 0; n < NB; n++) {
                s_vx[n][rz][32] = a * pvx[n][g]
                    + br * ((s_txx[n][rz + 1][33] - s_txx[n][rz + 1][32])
                          + (s_txz[n][rz + 1][33] - s_txz[n][rz][33]));
            }
        }
    }

    // ---- Phase 1b: vz_new on rel [-1..31]^2 at [rel+1] ----
    #pragma unroll
    for (int lz = tz; lz < 33; lz += 8) {
        int gz = z0 - 1 + lz;
        if (gz < 0) gz += NZ;
        const int rowc = gz * NX;
        {   const int lx = tx + 1;          // gx = x0+tx, never wraps
            const int g = rowc + x0 + tx;
            const float c   = 0.5f * DT * dmp[g];
            const float inv = __fdividef(1.0f, 1.0f + c);
            const float a   = (1.0f - c) * inv;
            const float br  = __fdividef(DT * inv * INVH, rho[g]);
            #pragma unroll
            for (int n = 0; n < NB; n++) {
                s_vz[n][lz][lx] = a * pvz[n][g]
                    + br * ((s_txz[n][lz][lx + 1] - s_txz[n][lz][lx])
                          + (s_tzz[n][lz + 1][lx] - s_tzz[n][lz][lx]));
            }
        }
        if (tx == 0) {   // lx = 0, gx = x0-1
            int gx = x0 - 1; if (gx < 0) gx += NX;
            const int g = rowc + gx;
            const float c   = 0.5f * DT * dmp[g];
            const float inv = __fdividef(1.0f, 1.0f + c);
            const float a   = (1.0f - c) * inv;
            const float br  = __fdividef(DT * inv * INVH, rho[g]);
            #pragma unroll
            for (int n = 0; n < NB; n++) {
                s_vz[n][lz][0] = a * pvz[n][g]
                    + br * ((s_txz[n][lz][1] - s_txz[n][lz][0])
                          + (s_tzz[n][lz + 1][0] - s_tzz[n][lz][0]));
            }
        }
    }
    __syncthreads();

    // ---- Phase 2: stress update + writes (interior 32x32) ----
    const int bplane = B * plane;
    #pragma unroll
    for (int z = tz; z < TS; z += 8) {
        const int g = (z0 + z) * NX + x0 + tx;
        const int x = tx;

        const float rr  = rho[g];
        const float fvs = vs[g];
        const float fvp = vp[g];
        const float mu  = rr * fvs * fvs;
        const float lam = rr * fvp * fvp - 2.0f * mu;
        const float lp2m = lam + 2.0f * mu;

        const float c   = 0.5f * DT * dmp[g];
        const float inv = __fdividef(1.0f, 1.0f + c);
        const float a   = (1.0f - c) * inv;
        const float bco = DT * inv;

        #pragma unroll
        for (int n = 0; n < NB; n++) {
            const float vx_c = s_vx[n][z][x];
            const float vz_c = s_vz[n][z + 1][x + 1];

            const float vx_x  = (s_vx[n][z][x + 1] - vx_c) * INVH;
            const float vx_zp = (s_vx[n][z + 1][x] - vx_c) * INVH;
            const float vz_z  = (vz_c - s_vz[n][z][x + 1]) * INVH;
            const float vz_xm = (vz_c - s_vz[n][z + 1][x]) * INVH;

            const float txxn = a * s_txx[n][z + 1][x + 1] + bco * (lp2m * vx_x + lam * vz_z);
            const float tzzn = a * s_tzz[n][z + 1][x + 1] + bco * (lp2m * vz_z + lam * vx_x);
            const float txzn = a * s_txz[n][z + 1][x + 1] + bco * (mu * (vx_zp + vz_xm));

            const int ob = (bb0 + n) * plane + g;
            __stcs(out + 0 * bplane + ob, vx_c);
            __stcs(out + 1 * bplane + ob, vz_c);
            __stcs(out + 2 * bplane + ob, txxn);
            __stcs(out + 3 * bplane + ob, tzzn);
            __stcs(out + 4 * bplane + ob, txzn);
        }
    }
}

extern "C" void kernel_launch(void* const* d_in, const int* in_sizes, int n_in,
                              void* d_out, int out_size) {
    const float* vp  = (const float*)d_in[0];
    const float* vs  = (const float*)d_in[1];
    const float* rho = (const float*)d_in[2];
    const float* vx  = (const float*)d_in[3];
    const float* vz  = (const float*)d_in[4];
    const float* txx = (const float*)d_in[5];
    const float* tzz = (const float*)d_in[6];
    const float* txz = (const float*)d_in[7];
    const float* dmp = (const float*)d_in[8];
    float* out = (float*)d_out;

    int plane = in_sizes[0];             // NZ * NX
    int B = in_sizes[3] / plane;         // batch from vx size
    int NX = 1;
    while (NX * NX < plane) NX <<= 1;    // square power-of-two grid (2048)
    int NZ = plane / NX;

    dim3 block(32, 8);
    dim3 grid((NX + TS - 1) / TS, (NZ + TS - 1) / TS, B / NB);
    wave_step_kernel<<<grid, block>>>(vp, vs, rho, vx, vz, txx, tzz, txz, dmp,
                                      out, B, NZ, NX);
}

// round 4
// speedup vs baseline: 1.6543x; 1.0390x over previous
#include <cuda_runtime.h>
#include <math.h>

#define DT   1e-3f
#define INVH 0.1f
#define TS   32
#define NB   2   // batches per block

__global__ __launch_bounds__(256, 6)
void wave_step_kernel(const float* __restrict__ vp,  const float* __restrict__ vs,
                      const float* __restrict__ rho,
                      const float* __restrict__ vx,  const float* __restrict__ vz,
                      const float* __restrict__ txx, const float* __restrict__ tzz,
                      const float* __restrict__ txz, const float* __restrict__ dmp,
                      float* __restrict__ out, int B, int NZ, int NX)
{
    // stress on rel [-1..32]^2 at [rel+1] -> [34][34] (cols 0..33 all used)
    __shared__ float s_txx[NB][34][34];   // after phase 1a, reused as s_vz
    __shared__ float s_tzz[NB][34][34];
    __shared__ float s_txz[NB][34][34];
    // vx_new on rel [0..32]^2 at [rel]
    __shared__ float s_vx[NB][33][34];
    // vz_new on rel [-1..31]^2 at [rel+1], aliased onto s_txx
#define s_vz s_txx

    const int bb0 = blockIdx.z * NB;
    const int z0  = blockIdx.y * TS;
    const int x0  = blockIdx.x * TS;
    const int tx  = threadIdx.x;   // 0..31
    const int tz  = threadIdx.y;   // 0..7
    const int plane = NZ * NX;
    const int boff  = bb0 * plane;

    const float* __restrict__ bvx  = vx  + boff;
    const float* __restrict__ bvz  = vz  + boff;
    const float* __restrict__ btxx = txx + boff;
    const float* __restrict__ btzz = tzz + boff;
    const float* __restrict__ btxz = txz + boff;

    // ---- Phase 0: stress halo rel [-1..32]^2 ----
    #pragma unroll
    for (int lz = tz; lz < 34; lz += 8) {
        int gz = z0 - 1 + lz;
        if (gz < 0) gz += NZ; else if (gz >= NZ) gz -= NZ;
        const int rowc = gz * NX;
        {   // interior columns lx = tx+1, gx = x0+tx (never wraps)
            const int g = rowc + x0 + tx;
            const int lx = tx + 1;
            #pragma unroll
            for (int n = 0; n < NB; n++) {
                s_txx[n][lz][lx] = btxx[n * plane + g];
                s_tzz[n][lz][lx] = btzz[n * plane + g];
                s_txz[n][lz][lx] = btxz[n * plane + g];
            }
        }
        if (tx < 2) {   // edges: lx=0 (gx=x0-1) and lx=33 (gx=x0+32)
            int gx = (tx == 0) ? (x0 - 1) : (x0 + 32);
            if (gx < 0) gx += NX; else if (gx >= NX) gx -= NX;
            const int lx = (tx == 0) ? 0 : 33;
            const int g = rowc + gx;
            #pragma unroll
            for (int n = 0; n < NB; n++) {
                s_txx[n][lz][lx] = btxx[n * plane + g];
                s_tzz[n][lz][lx] = btzz[n * plane + g];
                s_txz[n][lz][lx] = btxz[n * plane + g];
            }
        }
    }
    __syncthreads();

    // ---- Phase 1a: vx_new on rel [0..32]^2 (reads s_txx, s_txz) ----
    #pragma unroll
    for (int rz = tz; rz < 33; rz += 8) {
        int gz = z0 + rz;
        if (gz >= NZ) gz -= NZ;
        const int rowc = gz * NX;
        {   const int rx = tx;
            const int g = rowc + x0 + tx;
            const float c   = 0.5f * DT * dmp[g];
            const float inv = __fdividef(1.0f, 1.0f + c);
            const float a   = (1.0f - c) * inv;
            const float br  = __fdividef(DT * inv * INVH, rho[g]);
            #pragma unroll
            for (int n = 0; n < NB; n++) {
                s_vx[n][rz][rx] = a * bvx[n * plane + g]
                    + br * ((s_txx[n][rz + 1][rx + 1] - s_txx[n][rz + 1][rx])
                          + (s_txz[n][rz + 1][rx + 1] - s_txz[n][rz][rx + 1]));
            }
        }
        if (tx == 0) {   // rx = 32
            int gx = x0 + 32; if (gx >= NX) gx -= NX;
            const int g = rowc + gx;
            const float c   = 0.5f * DT * dmp[g];
            const float inv = __fdividef(1.0f, 1.0f + c);
            const float a   = (1.0f - c) * inv;
            const float br  = __fdividef(DT * inv * INVH, rho[g]);
            #pragma unroll
            for (int n = 0; n < NB; n++) {
                s_vx[n][rz][32] = a * bvx[n * plane + g]
                    + br * ((s_txx[n][rz + 1][33] - s_txx[n][rz + 1][32])
                          + (s_txz[n][rz + 1][33] - s_txz[n][rz][33]));
            }
        }
    }
    __syncthreads();   // all reads of s_txx done before s_vz overwrites it

    // ---- Phase 1b: vz_new on rel [-1..31]^2 at [rel+1] (reads s_txz, s_tzz;
    //      writes s_vz == s_txx) ----
    #pragma unroll
    for (int lz = tz; lz < 33; lz += 8) {
        int gz = z0 - 1 + lz;
        if (gz < 0) gz += NZ;
        const int rowc = gz * NX;
        {   const int lx = tx + 1;          // gx = x0+tx, never wraps
            const int g = rowc + x0 + tx;
            const float c   = 0.5f * DT * dmp[g];
            const float inv = __fdividef(1.0f, 1.0f + c);
            const float a   = (1.0f - c) * inv;
            const float br  = __fdividef(DT * inv * INVH, rho[g]);
            #pragma unroll
            for (int n = 0; n < NB; n++) {
                const float rhs = (s_txz[n][lz][lx + 1] - s_txz[n][lz][lx])
                                + (s_tzz[n][lz + 1][lx] - s_tzz[n][lz][lx]);
                s_vz[n][lz][lx] = a * bvz[n * plane + g] + br * rhs;
            }
        }
        if (tx == 0) {   // lx = 0, gx = x0-1
            int gx = x0 - 1; if (gx < 0) gx += NX;
            const int g = rowc + gx;
            const float c   = 0.5f * DT * dmp[g];
            const float inv = __fdividef(1.0f, 1.0f + c);
            const float a   = (1.0f - c) * inv;
            const float br  = __fdividef(DT * inv * INVH, rho[g]);
            #pragma unroll
            for (int n = 0; n < NB; n++) {
                const float rhs = (s_txz[n][lz][1] - s_txz[n][lz][0])
                                + (s_tzz[n][lz + 1][0] - s_tzz[n][lz][0]);
                s_vz[n][lz][0] = a * bvz[n * plane + g] + br * rhs;
            }
        }
    }
    __syncthreads();

    // ---- Phase 2: stress update + writes (interior 32x32) ----
    // txx center comes from a global re-read (L2-hot); tzz/txz centers from smem.
    const int bplane = B * plane;
    #pragma unroll
    for (int z = tz; z < TS; z += 8) {
        const int g = (z0 + z) * NX + x0 + tx;
        const int x = tx;

        const float rr  = rho[g];
        const float fvs = vs[g];
        const float fvp = vp[g];
        const float mu  = rr * fvs * fvs;
        const float lam = rr * fvp * fvp - 2.0f * mu;
        const float lp2m = lam + 2.0f * mu;

        const float c   = 0.5f * DT * dmp[g];
        const float inv = __fdividef(1.0f, 1.0f + c);
        const float a   = (1.0f - c) * inv;
        const float bco = DT * inv;

        #pragma unroll
        for (int n = 0; n < NB; n++) {
            const float vx_c = s_vx[n][z][x];
            const float vz_c = s_vz[n][z + 1][x + 1];

            const float vx_x  = (s_vx[n][z][x + 1] - vx_c) * INVH;
            const float vx_zp = (s_vx[n][z + 1][x] - vx_c) * INVH;
            const float vz_z  = (vz_c - s_vz[n][z][x + 1]) * INVH;
            const float vz_xm = (vz_c - s_vz[n][z + 1][x]) * INVH;

            const float txx_c = __ldg(btxx + n * plane + g);   // L2-hot re-read
            const float txxn = a * txx_c + bco * (lp2m * vx_x + lam * vz_z);
            const float tzzn = a * s_tzz[n][z + 1][x + 1] + bco * (lp2m * vz_z + lam * vx_x);
            const float txzn = a * s_txz[n][z + 1][x + 1] + bco * (mu * (vx_zp + vz_xm));

            const int ob = (bb0 + n) * plane + g;
            __stcs(out + 0 * bplane + ob, vx_c);
            __stcs(out + 1 * bplane + ob, vz_c);
            __stcs(out + 2 * bplane + ob, txxn);
            __stcs(out + 3 * bplane + ob, tzzn);
            __stcs(out + 4 * bplane + ob, txzn);
        }
    }
}

extern "C" void kernel_launch(void* const* d_in, const int* in_sizes, int n_in,
                              void* d_out, int out_size) {
    const float* vp  = (const float*)d_in[0];
    const float* vs  = (const float*)d_in[1];
    const float* rho = (const float*)d_in[2];
    const float* vx  = (const float*)d_in[3];
    const float* vz  = (const float*)d_in[4];
    const float* txx = (const float*)d_in[5];
    const float* tzz = (const float*)d_in[6];
    const float* txz = (const float*)d_in[7];
    const float* dmp = (const float*)d_in[8];
    float* out = (float*)d_out;

    int plane = in_sizes[0];             // NZ * NX
    int B = in_sizes[3] / plane;         // batch from vx size
    int NX = 1;
    while (NX * NX < plane) NX <<= 1;    // square power-of-two grid (2048)
    int NZ = plane / NX;

    dim3 block(32, 8);
    dim3 grid((NX + TS - 1) / TS, (NZ + TS - 1) / TS, B / NB);
    wave_step_kernel<<<grid, block>>>(vp, vs, rho, vx, vz, txx, tzz, txz, dmp,
                                      out, B, NZ, NX);
}

// round 5
// speedup vs baseline: 1.9576x; 1.1833x over previous
#include <cuda_runtime.h>
#include <math.h>

#define DT   1e-3f
#define INVH 0.1f

// ---------------- Kernel 1: velocity update (pure streaming) ----------------
__global__ __launch_bounds__(256)
void vel_kernel(const float* __restrict__ rho,
                const float* __restrict__ vx,  const float* __restrict__ vz,
                const float* __restrict__ txx, const float* __restrict__ tzz,
                const float* __restrict__ txz, const float* __restrict__ dmp,
                float* __restrict__ out, int B, int NZ, int NX)
{
    const int x = blockIdx.x * 32 + threadIdx.x;
    const int z = blockIdx.y * 8 + threadIdx.y;
    if (x >= NX || z >= NZ) return;
    const int plane = NZ * NX;
    const int g   = z * NX + x;
    const int xm  = (x == 0) ? NX - 1 : x - 1;
    const int xp  = (x == NX - 1) ? 0 : x + 1;
    const int zm  = (z == 0) ? NZ - 1 : z - 1;
    const int zp  = (z == NZ - 1) ? 0 : z + 1;
    const int gxm = z * NX + xm;
    const int gxp = z * NX + xp;
    const int gzm = zm * NX + x;
    const int gzp = zp * NX + x;

    const float c   = 0.5f * DT * dmp[g];
    const float inv = __fdividef(1.0f, 1.0f + c);
    const float a   = (1.0f - c) * inv;
    const float br  = __fdividef(DT * inv * INVH, rho[g]);

    float* __restrict__ ovz = out + B * plane;

    if (B == 4) {
        #pragma unroll
        for (int b = 0; b < 4; b++) {
            const int o = b * plane;
            const float vxn = a * vx[o + g]
                + br * ((txx[o + g] - txx[o + gxm]) + (txz[o + g] - txz[o + gzm]));
            const float vzn = a * vz[o + g]
                + br * ((txz[o + gxp] - txz[o + g]) + (tzz[o + gzp] - tzz[o + g]));
            out[o + g] = vxn;
            ovz[o + g] = vzn;
        }
    } else {
        for (int b = 0; b < B; b++) {
            const int o = b * plane;
            const float vxn = a * vx[o + g]
                + br * ((txx[o + g] - txx[o + gxm]) + (txz[o + g] - txz[o + gzm]));
            const float vzn = a * vz[o + g]
                + br * ((txz[o + gxp] - txz[o + g]) + (tzz[o + gzp] - tzz[o + g]));
            out[o + g] = vxn;
            ovz[o + g] = vzn;
        }
    }
}

// ---------------- Kernel 2: stress update (pure streaming) ----------------
__global__ __launch_bounds__(256)
void stress_kernel(const float* __restrict__ vp, const float* __restrict__ vs,
                   const float* __restrict__ rho,
                   const float* __restrict__ txx, const float* __restrict__ tzz,
                   const float* __restrict__ txz, const float* __restrict__ dmp,
                   float* __restrict__ out, int B, int NZ, int NX)
{
    const int x = blockIdx.x * 32 + threadIdx.x;
    const int z = blockIdx.y * 8 + threadIdx.y;
    if (x >= NX || z >= NZ) return;
    const int plane = NZ * NX;
    const int g   = z * NX + x;
    const int xm  = (x == 0) ? NX - 1 : x - 1;
    const int xp  = (x == NX - 1) ? 0 : x + 1;
    const int zm  = (z == 0) ? NZ - 1 : z - 1;
    const int zp  = (z == NZ - 1) ? 0 : z + 1;
    const int gxm = z * NX + xm;
    const int gxp = z * NX + xp;
    const int gzm = zm * NX + x;
    const int gzp = zp * NX + x;

    const float rr  = rho[g];
    const float fvs = vs[g];
    const float fvp = vp[g];
    const float mu   = rr * fvs * fvs;
    const float lam  = rr * fvp * fvp - 2.0f * mu;
    const float lp2m = lam + 2.0f * mu;

    const float c   = 0.5f * DT * dmp[g];
    const float inv = __fdividef(1.0f, 1.0f + c);
    const float a   = (1.0f - c) * inv;
    const float bco = DT * inv;

    const int bplane = B * plane;
    const float* __restrict__ nvx = out;              // vx_new written by K1
    const float* __restrict__ nvz = out + bplane;     // vz_new written by K1
    float* __restrict__ otxx = out + 2 * bplane;
    float* __restrict__ otzz = out + 3 * bplane;
    float* __restrict__ otxz = out + 4 * bplane;

    if (B == 4) {
        #pragma unroll
        for (int b = 0; b < 4; b++) {
            const int o = b * plane;
            const float vx_c  = nvx[o + g];
            const float vx_xp = nvx[o + gxp];
            const float vx_zp = nvx[o + gzp];
            const float vz_c  = nvz[o + g];
            const float vz_xm = nvz[o + gxm];
            const float vz_zm = nvz[o + gzm];

            const float vx_x = (vx_xp - vx_c) * INVH;
            const float vz_z = (vz_c - vz_zm) * INVH;

            const float txxn = a * txx[o + g] + bco * (lp2m * vx_x + lam * vz_z);
            const float tzzn = a * tzz[o + g] + bco * (lp2m * vz_z + lam * vx_x);
            const float txzn = a * txz[o + g]
                + bco * mu * ((vx_zp - vx_c) * INVH + (vz_c - vz_xm) * INVH);

            __stcs(otxx + o + g, txxn);
            __stcs(otzz + o + g, tzzn);
            __stcs(otxz + o + g, txzn);
        }
    } else {
        for (int b = 0; b < B; b++) {
            const int o = b * plane;
            const float vx_c  = nvx[o + g];
            const float vx_xp = nvx[o + gxp];
            const float vx_zp = nvx[o + gzp];
            const float vz_c  = nvz[o + g];
            const float vz_xm = nvz[o + gxm];
            const float vz_zm = nvz[o + gzm];

            const float vx_x = (vx_xp - vx_c) * INVH;
            const float vz_z = (vz_c - vz_zm) * INVH;

            const float txxn = a * txx[o + g] + bco * (lp2m * vx_x + lam * vz_z);
            const float tzzn = a * tzz[o + g] + bco * (lp2m * vz_z + lam * vx_x);
            const float txzn = a * txz[o + g]
                + bco * mu * ((vx_zp - vx_c) * INVH + (vz_c - vz_xm) * INVH);

            __stcs(otxx + o + g, txxn);
            __stcs(otzz + o + g, tzzn);
            __stcs(otxz + o + g, txzn);
        }
    }
}

extern "C" void kernel_launch(void* const* d_in, const int* in_sizes, int n_in,
                              void* d_out, int out_size) {
    const float* vp  = (const float*)d_in[0];
    const float* vs  = (const float*)d_in[1];
    const float* rho = (const float*)d_in[2];
    const float* vx  = (const float*)d_in[3];
    const float* vz  = (const float*)d_in[4];
    const float* txx = (const float*)d_in[5];
    const float* tzz = (const float*)d_in[6];
    const float* txz = (const float*)d_in[7];
    const float* dmp = (const float*)d_in[8];
    float* out = (float*)d_out;

    int plane = in_sizes[0];             // NZ * NX
    int B = in_sizes[3] / plane;         // batch from vx size
    int NX = 1;
    while (NX * NX < plane) NX <<= 1;    // square power-of-two grid (2048)
    int NZ = plane / NX;

    dim3 block(32, 8);
    dim3 grid((NX + 31) / 32, (NZ + 7) / 8);
    vel_kernel<<<grid, block>>>(rho, vx, vz, txx, tzz, txz, dmp, out, B, NZ, NX);
    stress_kernel<<<grid, block>>>(vp, vs, rho, txx, tzz, txz, dmp, out, B, NZ, NX);
}

// round 6
// speedup vs baseline: 2.4030x; 1.2275x over previous
#include <cuda_runtime.h>
#include <math.h>

#define DT   1e-3f
#define INVH 0.1f

__device__ __forceinline__ float4 ldf4(const float* p) {
    return *reinterpret_cast<const float4*>(p);
}

// ---------------- Kernel 1: velocity update (float4 streaming) ----------------
__global__ __launch_bounds__(256)
void vel_kernel(const float* __restrict__ rho,
                const float* __restrict__ vx,  const float* __restrict__ vz,
                const float* __restrict__ txx, const float* __restrict__ tzz,
                const float* __restrict__ txz, const float* __restrict__ dmp,
                float* __restrict__ out, int B, int NZ, int NX)
{
    const int x4 = (blockIdx.x * 32 + threadIdx.x) * 4;
    const int z  = blockIdx.y * 8 + threadIdx.y;
    if (x4 >= NX || z >= NZ) return;
    const int plane = NZ * NX;
    const int rowb = z * NX;
    const int g    = rowb + x4;
    const int gxm  = (x4 == 0)        ? rowb + NX - 1 : g - 1;   // scalar at x4-1
    const int gxp  = (x4 + 4 == NX)   ? rowb          : g + 4;   // scalar at x4+4
    const int gzm  = ((z == 0) ? NZ - 1 : z - 1) * NX + x4;
    const int gzp  = ((z == NZ - 1) ? 0 : z + 1) * NX + x4;

    const float4 d4 = ldf4(dmp + g);
    const float4 r4 = ldf4(rho + g);
    float a[4], br[4];
    {
        const float cc[4] = {0.5f * DT * d4.x, 0.5f * DT * d4.y,
                             0.5f * DT * d4.z, 0.5f * DT * d4.w};
        const float rr[4] = {r4.x, r4.y, r4.z, r4.w};
        #pragma unroll
        for (int i = 0; i < 4; i++) {
            const float inv = __fdividef(1.0f, 1.0f + cc[i]);
            a[i]  = (1.0f - cc[i]) * inv;
            br[i] = __fdividef(DT * inv * INVH, rr[i]);
        }
    }

    float* __restrict__ ovz = out + B * plane;

    #pragma unroll 1
    for (int b = 0; b < B; b++) {
        const int o = b * plane;
        const float4 t_xx   = ldf4(txx + o + g);
        const float  t_xx_m = txx[o + gxm];
        const float4 t_xz   = ldf4(txz + o + g);
        const float  t_xz_p = txz[o + gxp];
        const float4 t_xz_zm = ldf4(txz + o + gzm);
        const float4 t_zz   = ldf4(tzz + o + g);
        const float4 t_zz_zp = ldf4(tzz + o + gzp);
        const float4 v_x    = ldf4(vx + o + g);
        const float4 v_z    = ldf4(vz + o + g);

        float4 vxn, vzn;
        vxn.x = a[0] * v_x.x + br[0] * ((t_xx.x - t_xx_m) + (t_xz.x - t_xz_zm.x));
        vxn.y = a[1] * v_x.y + br[1] * ((t_xx.y - t_xx.x) + (t_xz.y - t_xz_zm.y));
        vxn.z = a[2] * v_x.z + br[2] * ((t_xx.z - t_xx.y) + (t_xz.z - t_xz_zm.z));
        vxn.w = a[3] * v_x.w + br[3] * ((t_xx.w - t_xx.z) + (t_xz.w - t_xz_zm.w));

        vzn.x = a[0] * v_z.x + br[0] * ((t_xz.y - t_xz.x) + (t_zz_zp.x - t_zz.x));
        vzn.y = a[1] * v_z.y + br[1] * ((t_xz.z - t_xz.y) + (t_zz_zp.y - t_zz.y));
        vzn.z = a[2] * v_z.z + br[2] * ((t_xz.w - t_xz.z) + (t_zz_zp.z - t_zz.z));
        vzn.w = a[3] * v_z.w + br[3] * ((t_xz_p - t_xz.w) + (t_zz_zp.w - t_zz.w));

        *reinterpret_cast<float4*>(out + o + g) = vxn;
        *reinterpret_cast<float4*>(ovz + o + g) = vzn;
    }
}

// ---------------- Kernel 2: stress update (float4 streaming) ----------------
__global__ __launch_bounds__(256)
void stress_kernel(const float* __restrict__ vp, const float* __restrict__ vs,
                   const float* __restrict__ rho,
                   const float* __restrict__ txx, const float* __restrict__ tzz,
                   const float* __restrict__ txz, const float* __restrict__ dmp,
                   float* __restrict__ out, int B, int NZ, int NX)
{
    const int x4 = (blockIdx.x * 32 + threadIdx.x) * 4;
    const int z  = blockIdx.y * 8 + threadIdx.y;
    if (x4 >= NX || z >= NZ) return;
    const int plane = NZ * NX;
    const int rowb = z * NX;
    const int g    = rowb + x4;
    const int gxm  = (x4 == 0)      ? rowb + NX - 1 : g - 1;
    const int gxp  = (x4 + 4 == NX) ? rowb          : g + 4;
    const int gzm  = ((z == 0) ? NZ - 1 : z - 1) * NX + x4;
    const int gzp  = ((z == NZ - 1) ? 0 : z + 1) * NX + x4;

    const float4 r4  = ldf4(rho + g);
    const float4 s4  = ldf4(vs + g);
    const float4 p4  = ldf4(vp + g);
    const float4 d4  = ldf4(dmp + g);

    float a[4], bco[4], mu[4], lam[4], lp2m[4];
    {
        const float rr[4] = {r4.x, r4.y, r4.z, r4.w};
        const float ss[4] = {s4.x, s4.y, s4.z, s4.w};
        const float pp[4] = {p4.x, p4.y, p4.z, p4.w};
        const float dd[4] = {d4.x, d4.y, d4.z, d4.w};
        #pragma unroll
        for (int i = 0; i < 4; i++) {
            mu[i]   = rr[i] * ss[i] * ss[i];
            lam[i]  = rr[i] * pp[i] * pp[i] - 2.0f * mu[i];
            lp2m[i] = lam[i] + 2.0f * mu[i];
            const float c   = 0.5f * DT * dd[i];
            const float inv = __fdividef(1.0f, 1.0f + c);
            a[i]   = (1.0f - c) * inv;
            bco[i] = DT * inv;
        }
    }

    const int bplane = B * plane;
    const float* __restrict__ nvx = out;
    const float* __restrict__ nvz = out + bplane;
    float* __restrict__ otxx = out + 2 * bplane;
    float* __restrict__ otzz = out + 3 * bplane;
    float* __restrict__ otxz = out + 4 * bplane;

    #pragma unroll 1
    for (int b = 0; b < B; b++) {
        const int o = b * plane;
        const float4 vxc   = ldf4(nvx + o + g);
        const float  vxp   = nvx[o + gxp];
        const float4 vxzp  = ldf4(nvx + o + gzp);
        const float4 vzc   = ldf4(nvz + o + g);
        const float  vzm   = nvz[o + gxm];
        const float4 vzzm  = ldf4(nvz + o + gzm);
        const float4 t_xx  = ldf4(txx + o + g);
        const float4 t_zz  = ldf4(tzz + o + g);
        const float4 t_xz  = ldf4(txz + o + g);

        const float vx_x[4] = {(vxc.y - vxc.x) * INVH, (vxc.z - vxc.y) * INVH,
                               (vxc.w - vxc.z) * INVH, (vxp  - vxc.w) * INVH};
        const float vz_z[4] = {(vzc.x - vzzm.x) * INVH, (vzc.y - vzzm.y) * INVH,
                               (vzc.z - vzzm.z) * INVH, (vzc.w - vzzm.w) * INVH};
        const float vx_zp[4] = {(vxzp.x - vxc.x) * INVH, (vxzp.y - vxc.y) * INVH,
                                (vxzp.z - vxc.z) * INVH, (vxzp.w - vxc.w) * INVH};
        const float vz_xm[4] = {(vzc.x - vzm) * INVH, (vzc.y - vzc.x) * INVH,
                                (vzc.z - vzc.y) * INVH, (vzc.w - vzc.z) * INVH};
        const float txxc[4] = {t_xx.x, t_xx.y, t_xx.z, t_xx.w};
        const float tzzc[4] = {t_zz.x, t_zz.y, t_zz.z, t_zz.w};
        const float txzc[4] = {t_xz.x, t_xz.y, t_xz.z, t_xz.w};

        float4 txxn, tzzn, txzn;
        float* pxx = &txxn.x; float* pzz = &tzzn.x; float* pxz = &txzn.x;
        #pragma unroll
        for (int i = 0; i < 4; i++) {
            pxx[i] = a[i] * txxc[i] + bco[i] * (lp2m[i] * vx_x[i] + lam[i] * vz_z[i]);
            pzz[i] = a[i] * tzzc[i] + bco[i] * (lp2m[i] * vz_z[i] + lam[i] * vx_x[i]);
            pxz[i] = a[i] * txzc[i] + bco[i] * mu[i] * (vx_zp[i] + vz_xm[i]);
        }
        __stcs(reinterpret_cast<float4*>(otxx + o + g), txxn);
        __stcs(reinterpret_cast<float4*>(otzz + o + g), tzzn);
        __stcs(reinterpret_cast<float4*>(otxz + o + g), txzn);
    }
}

extern "C" void kernel_launch(void* const* d_in, const int* in_sizes, int n_in,
                              void* d_out, int out_size) {
    const float* vp  = (const float*)d_in[0];
    const float* vs  = (const float*)d_in[1];
    const float* rho = (const float*)d_in[2];
    const float* vx  = (const float*)d_in[3];
    const float* vz  = (const float*)d_in[4];
    const float* txx = (const float*)d_in[5];
    const float* tzz = (const float*)d_in[6];
    const float* txz = (const float*)d_in[7];
    const float* dmp = (const float*)d_in[8];
    float* out = (float*)d_out;

    int plane = in_sizes[0];             // NZ * NX
    int B = in_sizes[3] / plane;         // batch from vx size
    int NX = 1;
    while (NX * NX < plane) NX <<= 1;    // square power-of-two grid (2048)
    int NZ = plane / NX;

    dim3 block(32, 8);
    dim3 grid((NX / 4 + 31) / 32, (NZ + 7) / 8);
    vel_kernel<<<grid, block>>>(rho, vx, vz, txx, tzz, txz, dmp, out, B, NZ, NX);
    stress_kernel<<<grid, block>>>(vp, vs, rho, txx, tzz, txz, dmp, out, B, NZ, NX);
}

// round 7
// speedup vs baseline: 2.8149x; 1.1714x over previous
#include <cuda_runtime.h>
#include <math.h>

#define DT   1e-3f
#define INVH 0.1f

__device__ __forceinline__ float4 ldf4(const float* p) {
    return *reinterpret_cast<const float4*>(p);
}

// One fused kernel: each thread owns a 4-wide x-quad at row z, loops over all
// batches. Velocities at rows z-1/z/z+1 are recomputed from stresses in
// registers (no smem, no barriers). Duplicate neighbor-row reads are L2-hot.
__global__ __launch_bounds__(256)
void fused_kernel(const float* __restrict__ vp,  const float* __restrict__ vs,
                  const float* __restrict__ rho,
                  const float* __restrict__ vx,  const float* __restrict__ vz,
                  const float* __restrict__ txx, const float* __restrict__ tzz,
                  const float* __restrict__ txz, const float* __restrict__ dmp,
                  float* __restrict__ out, int B, int NZ, int NX)
{
    const int x4 = (blockIdx.x * 32 + threadIdx.x) * 4;
    const int z  = blockIdx.y * 8 + threadIdx.y;
    if (x4 >= NX || z >= NZ) return;
    const int plane = NZ * NX;

    const int r0 = z * NX;
    const int rm = ((z == 0) ? NZ - 1 : z - 1) * NX;
    const int rp = ((z == NZ - 1) ? 0 : z + 1) * NX;
    const int xm  = (x4 == 0)      ? NX - 1 : x4 - 1;
    const int xp4 = (x4 + 4 == NX) ? 0      : x4 + 4;

    // ---------------- coefficients (batch-independent) ----------------
    // velocity coeffs: rows z (x4-1..x4+4), z-1 (quad), z+1 (quad)
    const float4 d0 = ldf4(dmp + r0 + x4);
    const float4 dM = ldf4(dmp + rm + x4);
    const float4 dP = ldf4(dmp + rp + x4);
    const float  d0m = dmp[r0 + xm], d0p = dmp[r0 + xp4];
    const float4 q0 = ldf4(rho + r0 + x4);
    const float4 qM = ldf4(rho + rm + x4);
    const float4 qP = ldf4(rho + rp + x4);
    const float  q0m = rho[r0 + xm], q0p = rho[r0 + xp4];

    float a0[4], br0[4], aM[4], brM[4], aP[4], brP[4], bco[4];
    float a0m, br0m, a0p, br0p;
    {
        const float dd0[4] = {d0.x, d0.y, d0.z, d0.w};
        const float ddM[4] = {dM.x, dM.y, dM.z, dM.w};
        const float ddP[4] = {dP.x, dP.y, dP.z, dP.w};
        const float qq0[4] = {q0.x, q0.y, q0.z, q0.w};
        const float qqM[4] = {qM.x, qM.y, qM.z, qM.w};
        const float qqP[4] = {qP.x, qP.y, qP.z, qP.w};
        #pragma unroll
        for (int i = 0; i < 4; i++) {
            float c, inv;
            c = 0.5f * DT * dd0[i]; inv = __fdividef(1.0f, 1.0f + c);
            a0[i] = (1.0f - c) * inv; bco[i] = DT * inv;
            br0[i] = __fdividef(DT * inv * INVH, qq0[i]);
            c = 0.5f * DT * ddM[i]; inv = __fdividef(1.0f, 1.0f + c);
            aM[i] = (1.0f - c) * inv;
            brM[i] = __fdividef(DT * inv * INVH, qqM[i]);
            c = 0.5f * DT * ddP[i]; inv = __fdividef(1.0f, 1.0f + c);
            aP[i] = (1.0f - c) * inv;
            brP[i] = __fdividef(DT * inv * INVH, qqP[i]);
        }
        float c, inv;
        c = 0.5f * DT * d0m; inv = __fdividef(1.0f, 1.0f + c);
        a0m = (1.0f - c) * inv; br0m = __fdividef(DT * inv * INVH, q0m);
        c = 0.5f * DT * d0p; inv = __fdividef(1.0f, 1.0f + c);
        a0p = (1.0f - c) * inv; br0p = __fdividef(DT * inv * INVH, q0p);
    }
    // stress material coeffs at (z, quad)
    float mu[4], lam[4], lp2m[4];
    {
        const float4 s4 = ldf4(vs + r0 + x4);
        const float4 p4 = ldf4(vp + r0 + x4);
        const float ss[4] = {s4.x, s4.y, s4.z, s4.w};
        const float pp[4] = {p4.x, p4.y, p4.z, p4.w};
        const float qq[4] = {q0.x, q0.y, q0.z, q0.w};
        #pragma unroll
        for (int i = 0; i < 4; i++) {
            mu[i]   = qq[i] * ss[i] * ss[i];
            lam[i]  = qq[i] * pp[i] * pp[i] - 2.0f * mu[i];
            lp2m[i] = lam[i] + 2.0f * mu[i];
        }
    }

    const int bplane = B * plane;
    float* __restrict__ ovx  = out;
    float* __restrict__ ovz  = out + bplane;
    float* __restrict__ otxx = out + 2 * bplane;
    float* __restrict__ otzz = out + 3 * bplane;
    float* __restrict__ otxz = out + 4 * bplane;

    #pragma unroll 1
    for (int b = 0; b < B; b++) {
        const int o = b * plane;

        // ---- stress loads ----
        const float4 txx0 = ldf4(txx + o + r0 + x4);
        const float  txx0m = txx[o + r0 + xm];
        const float  txx0p = txx[o + r0 + xp4];
        const float4 txxP = ldf4(txx + o + rp + x4);
        const float  txxPm = txx[o + rp + xm];

        const float4 txz0 = ldf4(txz + o + r0 + x4);
        const float  txz0m = txz[o + r0 + xm];
        const float  txz0p = txz[o + r0 + xp4];
        const float4 txzM = ldf4(txz + o + rm + x4);
        const float  txzMp = txz[o + rm + xp4];
        const float4 txzP = ldf4(txz + o + rp + x4);

        const float4 tzz0 = ldf4(tzz + o + r0 + x4);
        const float  tzz0m = tzz[o + r0 + xm];
        const float4 tzzP = ldf4(tzz + o + rp + x4);
        const float  tzzPm = tzz[o + rp + xm];
        const float4 tzzM = ldf4(tzz + o + rm + x4);

        const float4 vx0 = ldf4(vx + o + r0 + x4);
        const float  vx0p = vx[o + r0 + xp4];
        const float4 vxP = ldf4(vx + o + rp + x4);
        const float4 vz0 = ldf4(vz + o + r0 + x4);
        const float  vz0m = vz[o + r0 + xm];
        const float4 vzM = ldf4(vz + o + rm + x4);

        // ---- arrays along x ----
        const float txxr0[6] = {txx0m, txx0.x, txx0.y, txx0.z, txx0.w, txx0p}; // x4-1..x4+4
        const float txzr0[6] = {txz0m, txz0.x, txz0.y, txz0.z, txz0.w, txz0p}; // x4-1..x4+4
        const float txzrm[5] = {txzM.x, txzM.y, txzM.z, txzM.w, txzMp};        // x4..x4+4
        const float txxrp[5] = {txxPm, txxP.x, txxP.y, txxP.z, txxP.w};        // x4-1..x4+3
        const float tzzr0[5] = {tzz0m, tzz0.x, tzz0.y, tzz0.z, tzz0.w};        // x4-1..x4+3
        const float tzzrp[5] = {tzzPm, tzzP.x, tzzP.y, tzzP.z, tzzP.w};        // x4-1..x4+3
        const float vxr0[5]  = {vx0.x, vx0.y, vx0.z, vx0.w, vx0p};             // x4..x4+4
        const float vzr0[5]  = {vz0m, vz0.x, vz0.y, vz0.z, vz0.w};             // x4-1..x4+3
        const float av0[5]   = {a0[0], a0[1], a0[2], a0[3], a0p};
        const float brv0[5]  = {br0[0], br0[1], br0[2], br0[3], br0p};
        const float av0m[5]  = {a0m, a0[0], a0[1], a0[2], a0[3]};
        const float brv0m[5] = {br0m, br0[0], br0[1], br0[2], br0[3]};

        // ---- velocity recompute ----
        // vxnA[i]: vx_new at (z, x4+i), i=0..4
        float vxnA[5];
        #pragma unroll
        for (int i = 0; i < 5; i++)
            vxnA[i] = av0[i] * vxr0[i]
                    + brv0[i] * ((txxr0[i + 1] - txxr0[i]) + (txzr0[i + 1] - txzrm[i]));
        // vxnB[i]: vx_new at (z+1, x4+i), i=0..3
        const float vxrp[4]  = {vxP.x, vxP.y, vxP.z, vxP.w};
        const float txzp_[4] = {txzP.x, txzP.y, txzP.z, txzP.w};
        float vxnB[4];
        #pragma unroll
        for (int i = 0; i < 4; i++)
            vxnB[i] = aP[i] * vxrp[i]
                    + brP[i] * ((txxrp[i + 1] - txxrp[i]) + (txzp_[i] - txzr0[i + 1]));
        // vznA[j]: vz_new at (z, x4-1+j), j=0..4
        float vznA[5];
        #pragma unroll
        for (int j = 0; j < 5; j++)
            vznA[j] = av0m[j] * vzr0[j]
                    + brv0m[j] * ((txzr0[j + 1] - txzr0[j]) + (tzzrp[j] - tzzr0[j]));
        // vznB[i]: vz_new at (z-1, x4+i), i=0..3
        const float vzrm[4] = {vzM.x, vzM.y, vzM.z, vzM.w};
        const float tzzm_[4] = {tzzM.x, tzzM.y, tzzM.z, tzzM.w};
        const float tzz0_[4] = {tzz0.x, tzz0.y, tzz0.z, tzz0.w};
        float vznB[4];
        #pragma unroll
        for (int i = 0; i < 4; i++)
            vznB[i] = aM[i] * vzrm[i]
                    + brM[i] * ((txzrm[i + 1] - txzrm[i]) + (tzz0_[i] - tzzm_[i]));

        // ---- stress update + writes ----
        const float txx0_[4] = {txx0.x, txx0.y, txx0.z, txx0.w};
        const float txz0_[4] = {txz0.x, txz0.y, txz0.z, txz0.w};
        float4 vxn4, vzn4, txxn4, tzzn4, txzn4;
        float* pvx = &vxn4.x;  float* pvz = &vzn4.x;
        float* pxx = &txxn4.x; float* pzz = &tzzn4.x; float* pxz = &txzn4.x;
        #pragma unroll
        for (int i = 0; i < 4; i++) {
            const float vx_x  = (vxnA[i + 1] - vxnA[i]) * INVH;
            const float vz_z  = (vznA[i + 1] - vznB[i]) * INVH;
            const float vx_zp = (vxnB[i] - vxnA[i]) * INVH;
            const float vz_xm = (vznA[i + 1] - vznA[i]) * INVH;
            pvx[i] = vxnA[i];
            pvz[i] = vznA[i + 1];
            pxx[i] = a0[i] * txx0_[i] + bco[i] * (lp2m[i] * vx_x + lam[i] * vz_z);
            pzz[i] = a0[i] * tzz0_[i] + bco[i] * (lp2m[i] * vz_z + lam[i] * vx_x);
            pxz[i] = a0[i] * txz0_[i] + bco[i] * (mu[i] * (vx_zp + vz_xm));
        }
        __stcs(reinterpret_cast<float4*>(ovx  + o + r0 + x4), vxn4);
        __stcs(reinterpret_cast<float4*>(ovz  + o + r0 + x4), vzn4);
        __stcs(reinterpret_cast<float4*>(otxx + o + r0 + x4), txxn4);
        __stcs(reinterpret_cast<float4*>(otzz + o + r0 + x4), tzzn4);
        __stcs(reinterpret_cast<float4*>(otxz + o + r0 + x4), txzn4);
    }
}

extern "C" void kernel_launch(void* const* d_in, const int* in_sizes, int n_in,
                              void* d_out, int out_size) {
    const float* vp  = (const float*)d_in[0];
    const float* vs  = (const float*)d_in[1];
    const float* rho = (const float*)d_in[2];
    const float* vx  = (const float*)d_in[3];
    const float* vz  = (const float*)d_in[4];
    const float* txx = (const float*)d_in[5];
    const float* tzz = (const float*)d_in[6];
    const float* txz = (const float*)d_in[7];
    const float* dmp = (const float*)d_in[8];
    float* out = (float*)d_out;

    int plane = in_sizes[0];             // NZ * NX
    int B = in_sizes[3] / plane;         // batch from vx size
    int NX = 1;
    while (NX * NX < plane) NX <<= 1;    // square power-of-two grid (2048)
    int NZ = plane / NX;

    dim3 block(32, 8);
    dim3 grid((NX / 4 + 31) / 32, (NZ + 7) / 8);
    fused_kernel<<<grid, block>>>(vp, vs, rho, vx, vz, txx, tzz, txz, dmp,
                                  out, B, NZ, NX);
}